// round 1
// baseline (speedup 1.0000x reference)
#include <cuda_runtime.h>

#define NN   50000
#define EE   800000
#define DIN  128
#define DHID 128
#define DOUT 64

// ---------------- scratch (no allocations allowed) ----------------
__device__ int   g_cnt[NN];
__device__ int   g_off[NN + 1];
__device__ int   g_cursor[NN];
__device__ int   g_csr[EE];
__device__ float g_mean[NN * DHID];
__device__ float g_h0[NN * DHID];
__device__ float g_h1[NN * DHID];
__device__ float g_W0[256 * DHID];   // [Ws0; Wn0]
__device__ float g_W1[256 * DHID];   // [Ws1; Wn1]
__device__ float g_W2[256 * DOUT];   // [Ws2; Wn2]

// ---------------- CSR build ----------------
__global__ void k_zero() {
    int i = blockIdx.x * blockDim.x + threadIdx.x;
    if (i < NN) g_cnt[i] = 0;
}

__global__ void k_hist(const int* __restrict__ dst) {
    int e = blockIdx.x * blockDim.x + threadIdx.x;
    if (e < EE) atomicAdd(&g_cnt[dst[e]], 1);
}

// single-block exclusive scan over g_cnt -> g_off, g_cursor
__global__ void k_scan() {
    __shared__ int ss[1024];
    int t = threadIdx.x;
    const int CH = (NN + 1023) / 1024;   // 49
    int s = t * CH;
    int e = min(s + CH, NN);
    int local = 0;
    for (int i = s; i < e; ++i) local += g_cnt[i];
    ss[t] = local;
    __syncthreads();
    // Hillis-Steele inclusive scan
    for (int d = 1; d < 1024; d <<= 1) {
        int v = (t >= d) ? ss[t - d] : 0;
        __syncthreads();
        ss[t] += v;
        __syncthreads();
    }
    int run = (t > 0) ? ss[t - 1] : 0;
    for (int i = s; i < e; ++i) {
        g_off[i] = run;
        g_cursor[i] = run;
        run += g_cnt[i];
    }
    if (t == 0) g_off[NN] = EE;
}

__global__ void k_scatter(const int* __restrict__ src, const int* __restrict__ dst) {
    int e = blockIdx.x * blockDim.x + threadIdx.x;
    if (e < EE) {
        int p = atomicAdd(&g_cursor[dst[e]], 1);
        g_csr[p] = src[e];
    }
}

// ---------------- weight concat: Wc[256][dout] = [Ws ; Wn] ----------------
__global__ void k_concatW(const float* __restrict__ Ws0, const float* __restrict__ Wn0,
                          const float* __restrict__ Ws1, const float* __restrict__ Wn1,
                          const float* __restrict__ Ws2, const float* __restrict__ Wn2) {
    int i = blockIdx.x * blockDim.x + threadIdx.x;
    if (i < 128 * DHID) {
        g_W0[i] = Ws0[i];  g_W0[128 * DHID + i] = Wn0[i];
        g_W1[i] = Ws1[i];  g_W1[128 * DHID + i] = Wn1[i];
    }
    if (i < 128 * DOUT) {
        g_W2[i] = Ws2[i];  g_W2[128 * DOUT + i] = Wn2[i];
    }
}

// ---------------- mean aggregation: one node per 128-thread block ----------------
// hsel: -1 -> hext (layer-0 input x), 0 -> g_h0, 1 -> g_h1
__global__ void k_agg(const float* __restrict__ hext, int hsel) {
    const float* __restrict__ h =
        (hsel == 0) ? g_h0 : (hsel == 1) ? g_h1 : hext;
    int n = blockIdx.x;
    int t = threadIdx.x;           // 0..127 = feature lane
    int s0 = g_off[n], s1 = g_off[n + 1];
    float sum = 0.f;
#pragma unroll 4
    for (int i = s0; i < s1; ++i) {
        int sidx = g_csr[i];       // uniform per block -> L1 broadcast
        sum += __ldg(&h[sidx * DHID + t]);
    }
    int d = s1 - s0;
    float inv = 1.0f / (float)(d > 0 ? d : 1);
    g_mean[n * DHID + t] = sum * inv;
}

// ---------------- fused GEMM: C = [A1 | g_mean] @ Wc + b (+relu) ----------------
// 64x64 tile, 256 threads, 4x4 microtile, K=256 (first 128 from A1, last 128 from g_mean)
__global__ void k_gemm(const float* __restrict__ A1ext, int asel, int wsel,
                       const float* __restrict__ bias,
                       float* __restrict__ Cext, int csel,
                       int dout, int relu) {
    const float* __restrict__ A1 =
        (asel == 0) ? g_h0 : (asel == 1) ? g_h1 : A1ext;
    const float* __restrict__ W =
        (wsel == 0) ? g_W0 : (wsel == 1) ? g_W1 : g_W2;
    float* __restrict__ C =
        (csel == 0) ? g_h0 : (csel == 1) ? g_h1 : Cext;

    __shared__ float As[16][64];
    __shared__ float Bs[16][64];

    int tid = threadIdx.x;               // 256
    int bm = blockIdx.x * 64;
    int bn = blockIdx.y * 64;
    int tx = tid & 15;                   // 0..15
    int ty = tid >> 4;                   // 0..15

    float acc[4][4];
#pragma unroll
    for (int i = 0; i < 4; ++i)
#pragma unroll
        for (int j = 0; j < 4; ++j) acc[i][j] = 0.f;

    int arow = tid >> 2;                 // 0..63
    int ac4  = (tid & 3) << 2;           // 0,4,8,12
    int wrow = tid >> 4;                 // 0..15
    int wc4  = (tid & 15) << 2;          // 0..60

    for (int kt = 0; kt < 16; ++kt) {
        const float* __restrict__ A = (kt < 8) ? A1 : g_mean;
        int k0 = (kt & 7) << 4;          // 0..112

        int grow = bm + arow;
        float4 av = make_float4(0.f, 0.f, 0.f, 0.f);
        if (grow < NN)
            av = *reinterpret_cast<const float4*>(A + grow * 128 + k0 + ac4);
        As[ac4 + 0][arow] = av.x;
        As[ac4 + 1][arow] = av.y;
        As[ac4 + 2][arow] = av.z;
        As[ac4 + 3][arow] = av.w;

        float4 wv = *reinterpret_cast<const float4*>(
            W + (kt * 16 + wrow) * dout + bn + wc4);
        *reinterpret_cast<float4*>(&Bs[wrow][wc4]) = wv;

        __syncthreads();

#pragma unroll
        for (int k = 0; k < 16; ++k) {
            float a[4], b[4];
#pragma unroll
            for (int i = 0; i < 4; ++i) a[i] = As[k][(ty << 2) + i];
#pragma unroll
            for (int j = 0; j < 4; ++j) b[j] = Bs[k][(tx << 2) + j];
#pragma unroll
            for (int i = 0; i < 4; ++i)
#pragma unroll
                for (int j = 0; j < 4; ++j) acc[i][j] += a[i] * b[j];
        }
        __syncthreads();
    }

#pragma unroll
    for (int i = 0; i < 4; ++i) {
        int row = bm + (ty << 2) + i;
        if (row >= NN) continue;
#pragma unroll
        for (int j = 0; j < 4; ++j) {
            int col = bn + (tx << 2) + j;
            float v = acc[i][j] + __ldg(&bias[col]);
            if (relu) v = fmaxf(v, 0.f);
            C[row * dout + col] = v;
        }
    }
}

// ---------------- launch ----------------
extern "C" void kernel_launch(void* const* d_in, const int* in_sizes, int n_in,
                              void* d_out, int out_size) {
    const float* x   = (const float*)d_in[0];
    const int*   src = (const int*)d_in[1];
    const int*   dst = (const int*)d_in[2];
    const float* Ws0 = (const float*)d_in[3];
    const float* Wn0 = (const float*)d_in[4];
    const float* b0  = (const float*)d_in[5];
    const float* Ws1 = (const float*)d_in[6];
    const float* Wn1 = (const float*)d_in[7];
    const float* b1  = (const float*)d_in[8];
    const float* Ws2 = (const float*)d_in[9];
    const float* Wn2 = (const float*)d_in[10];
    const float* b2  = (const float*)d_in[11];
    float* out = (float*)d_out;

    // CSR build
    k_zero<<<(NN + 255) / 256, 256>>>();
    k_hist<<<(EE + 255) / 256, 256>>>(dst);
    k_scan<<<1, 1024>>>();
    k_scatter<<<(EE + 255) / 256, 256>>>(src, dst);
    k_concatW<<<(128 * DHID + 255) / 256, 256>>>(Ws0, Wn0, Ws1, Wn1, Ws2, Wn2);

    dim3 g1((NN + 63) / 64, 2);   // dout = 128
    dim3 g2((NN + 63) / 64, 1);   // dout = 64

    // Layer 0: h0 = relu(x@Ws0 + mean(x)@Wn0 + b0)
    k_agg<<<NN, 128>>>(x, -1);
    k_gemm<<<g1, 256>>>(x, -1, 0, b0, nullptr, 0, DHID, 1);

    // Layer 1: h1 = relu(h0@Ws1 + mean(h0)@Wn1 + b1)
    k_agg<<<NN, 128>>>(nullptr, 0);
    k_gemm<<<g1, 256>>>(nullptr, 0, 1, b1, nullptr, 1, DHID, 1);

    // Layer 2: out = h1@Ws2 + mean(h1)@Wn2 + b2
    k_agg<<<NN, 128>>>(nullptr, 1);
    k_gemm<<<g2, 256>>>(nullptr, 1, 2, b2, out, 2, DOUT, 0);
}

// round 2
// speedup vs baseline: 1.3651x; 1.3651x over previous
#include <cuda_runtime.h>
#include <cstdint>

#define NN   50000
#define EE   800000

// ---------------- scratch (no allocations allowed) ----------------
__device__ int   g_cnt[NN];
__device__ int   g_off[NN + 1];
__device__ int   g_cur[NN];
__device__ int   g_csr[EE];
__device__ float g_T[NN * 256];       // per-layer GEMM output [self | neigh]
__device__ float g_h0[NN * 128];
__device__ float g_h1[NN * 128];
__device__ float g_W0[128 * 256];     // [Ws0 | Wn0] column-concat
__device__ float g_W1[128 * 256];
__device__ float g_W2[128 * 128];     // [Ws2 | Wn2]

// ---------------- CSR build ----------------
__global__ void k_zero() {
    int i = blockIdx.x * blockDim.x + threadIdx.x;
    if (i < NN) g_cnt[i] = 0;
}

__global__ void k_hist(const int* __restrict__ dst) {
    int e = blockIdx.x * blockDim.x + threadIdx.x;
    if (e < EE) atomicAdd(&g_cnt[dst[e]], 1);
}

__global__ void k_scan() {
    __shared__ int ss[1024];
    int t = threadIdx.x;
    const int CH = (NN + 1023) / 1024;
    int s = t * CH;
    int e = min(s + CH, NN);
    int local = 0;
    for (int i = s; i < e; ++i) local += g_cnt[i];
    ss[t] = local;
    __syncthreads();
    for (int d = 1; d < 1024; d <<= 1) {
        int v = (t >= d) ? ss[t - d] : 0;
        __syncthreads();
        ss[t] += v;
        __syncthreads();
    }
    int run = (t > 0) ? ss[t - 1] : 0;
    for (int i = s; i < e; ++i) {
        g_off[i] = run;
        g_cur[i] = run;
        run += g_cnt[i];
    }
    if (t == 0) g_off[NN] = EE;
}

__global__ void k_scatter(const int* __restrict__ src, const int* __restrict__ dst) {
    int e = blockIdx.x * blockDim.x + threadIdx.x;
    if (e < EE) {
        int p = atomicAdd(&g_cur[dst[e]], 1);
        g_csr[p] = src[e];
    }
}

// ---------------- weight concat (columns): Wc[k][0:d]=Ws[k], Wc[k][d:2d]=Wn[k] --
__global__ void k_concatW(const float* __restrict__ Ws0, const float* __restrict__ Wn0,
                          const float* __restrict__ Ws1, const float* __restrict__ Wn1,
                          const float* __restrict__ Ws2, const float* __restrict__ Wn2) {
    int i = blockIdx.x * blockDim.x + threadIdx.x;
    if (i < 128 * 128) {
        int k = i >> 7, c = i & 127;
        g_W0[k * 256 + c]       = Ws0[i];
        g_W0[k * 256 + 128 + c] = Wn0[i];
        g_W1[k * 256 + c]       = Ws1[i];
        g_W1[k * 256 + 128 + c] = Wn1[i];
    }
    if (i < 128 * 64) {
        int k = i >> 6, c = i & 63;
        g_W2[k * 128 + c]      = Ws2[i];
        g_W2[k * 128 + 64 + c] = Wn2[i];
    }
}

// ---------------- tf32 helpers ----------------
__device__ __forceinline__ uint32_t f2tf(float x) {
    uint32_t r;
    asm("cvt.rna.tf32.f32 %0, %1;" : "=r"(r) : "f"(x));
    return r;
}

__device__ __forceinline__ void mma8(float* c, const uint32_t* a, const uint32_t* b) {
    asm volatile(
        "mma.sync.aligned.m16n8k8.row.col.f32.tf32.tf32.f32 "
        "{%0,%1,%2,%3}, {%4,%5,%6,%7}, {%8,%9}, {%0,%1,%2,%3};\n"
        : "+f"(c[0]), "+f"(c[1]), "+f"(c[2]), "+f"(c[3])
        : "r"(a[0]), "r"(a[1]), "r"(a[2]), "r"(a[3]), "r"(b[0]), "r"(b[1]));
}

// ---------------- GEMM: T[M,nout] = A[M,128] @ W[128,nout] ----------------
// 128x64 block tile, 256 thr = 8 warps (4x2), warp tile 32x32 = 2x4 mma tiles.
// 3xTF32 split for ~fp32 accuracy.
__global__ __launch_bounds__(256) void k_gemm(const float* __restrict__ Aext,
                                              int asel, int wsel, int nout) {
    const float* __restrict__ A =
        (asel == 0) ? g_h0 : (asel == 1) ? g_h1 : Aext;
    const float* __restrict__ W =
        (wsel == 0) ? g_W0 : (wsel == 1) ? g_W1 : g_W2;

    __shared__ float As[128][36];   // stride 36: bank = 4m+k distinct
    __shared__ float Bs[32][72];    // stride 72: bank = 8k+n distinct

    int tid  = threadIdx.x;
    int bm   = blockIdx.x * 128;
    int bn   = blockIdx.y * 64;
    int warp = tid >> 5, lane = tid & 31;
    int wm = (warp & 3) * 32;       // warp M offset
    int wn = (warp >> 2) * 32;      // warp N offset
    int gi = lane >> 2;             // group id 0..7
    int ti = lane & 3;              // thread-in-group 0..3

    float c[2][4][4];
#pragma unroll
    for (int mt = 0; mt < 2; ++mt)
#pragma unroll
        for (int nt = 0; nt < 4; ++nt)
#pragma unroll
            for (int i = 0; i < 4; ++i) c[mt][nt][i] = 0.f;

    for (int kc = 0; kc < 4; ++kc) {
        // stage A chunk 128x32
#pragma unroll
        for (int r = 0; r < 4; ++r) {
            int idx = tid + r * 256;
            int row = idx >> 3;
            int f4  = (idx & 7) << 2;
            int gr  = bm + row;
            float4 v = make_float4(0.f, 0.f, 0.f, 0.f);
            if (gr < NN)
                v = *reinterpret_cast<const float4*>(A + gr * 128 + kc * 32 + f4);
            As[row][f4 + 0] = v.x;
            As[row][f4 + 1] = v.y;
            As[row][f4 + 2] = v.z;
            As[row][f4 + 3] = v.w;
        }
        // stage W chunk 32x64
#pragma unroll
        for (int r = 0; r < 2; ++r) {
            int idx = tid + r * 256;
            int row = idx >> 4;
            int f4  = (idx & 15) << 2;
            float4 v = *reinterpret_cast<const float4*>(
                W + (kc * 32 + row) * nout + bn + f4);
            Bs[row][f4 + 0] = v.x;
            Bs[row][f4 + 1] = v.y;
            Bs[row][f4 + 2] = v.z;
            Bs[row][f4 + 3] = v.w;
        }
        __syncthreads();

#pragma unroll
        for (int k8 = 0; k8 < 4; ++k8) {
            int kb = k8 * 8;
            uint32_t ahi[2][4], alo[2][4];
#pragma unroll
            for (int mt = 0; mt < 2; ++mt) {
                int rb = wm + mt * 16 + gi;
                float a0 = As[rb][kb + ti];
                float a1 = As[rb + 8][kb + ti];
                float a2 = As[rb][kb + ti + 4];
                float a3 = As[rb + 8][kb + ti + 4];
                ahi[mt][0] = f2tf(a0); alo[mt][0] = f2tf(a0 - __uint_as_float(ahi[mt][0]));
                ahi[mt][1] = f2tf(a1); alo[mt][1] = f2tf(a1 - __uint_as_float(ahi[mt][1]));
                ahi[mt][2] = f2tf(a2); alo[mt][2] = f2tf(a2 - __uint_as_float(ahi[mt][2]));
                ahi[mt][3] = f2tf(a3); alo[mt][3] = f2tf(a3 - __uint_as_float(ahi[mt][3]));
            }
            uint32_t bhi[4][2], blo[4][2];
#pragma unroll
            for (int nt = 0; nt < 4; ++nt) {
                int cb = wn + nt * 8 + gi;
                float b0 = Bs[kb + ti][cb];
                float b1 = Bs[kb + ti + 4][cb];
                bhi[nt][0] = f2tf(b0); blo[nt][0] = f2tf(b0 - __uint_as_float(bhi[nt][0]));
                bhi[nt][1] = f2tf(b1); blo[nt][1] = f2tf(b1 - __uint_as_float(bhi[nt][1]));
            }
#pragma unroll
            for (int mt = 0; mt < 2; ++mt)
#pragma unroll
                for (int nt = 0; nt < 4; ++nt) {
                    mma8(c[mt][nt], ahi[mt], bhi[nt]);
                    mma8(c[mt][nt], alo[mt], bhi[nt]);
                    mma8(c[mt][nt], ahi[mt], blo[nt]);
                }
        }
        __syncthreads();
    }

    // epilogue: raw store (bias/relu fused into k_finish)
#pragma unroll
    for (int mt = 0; mt < 2; ++mt) {
#pragma unroll
        for (int nt = 0; nt < 4; ++nt) {
            int row = bm + wm + mt * 16 + gi;
            int col = bn + wn + nt * 8 + ti * 2;
            if (row < NN) {
                g_T[row * nout + col]     = c[mt][nt][0];
                g_T[row * nout + col + 1] = c[mt][nt][1];
            }
            if (row + 8 < NN) {
                g_T[(row + 8) * nout + col]     = c[mt][nt][2];
                g_T[(row + 8) * nout + col + 1] = c[mt][nt][3];
            }
        }
    }
}

// ---------------- finish: out[n] = relu?(T[n,self] + mean_s T[s,neigh] + b) ----
// warp per node, float4 lanes. mode: 0 -> g_h0 (d=128), 1 -> g_h1, 2 -> ext (d=64)
__global__ __launch_bounds__(128) void k_finish(const float* __restrict__ bias,
                                                float* __restrict__ outext, int mode) {
    int warp = threadIdx.x >> 5, lane = threadIdx.x & 31;
    int n = blockIdx.x * 4 + warp;
    if (n >= NN) return;
    int s0 = g_off[n], s1 = g_off[n + 1];
    float inv = 1.0f / (float)((s1 - s0) > 0 ? (s1 - s0) : 1);

    if (mode < 2) {
        float* __restrict__ dsta = mode ? g_h1 : g_h0;
        float4 acc = make_float4(0.f, 0.f, 0.f, 0.f);
        for (int i = s0; i < s1; ++i) {
            int s = g_csr[i];
            float4 v = *reinterpret_cast<const float4*>(g_T + s * 256 + 128 + lane * 4);
            acc.x += v.x; acc.y += v.y; acc.z += v.z; acc.w += v.w;
        }
        float4 p = *reinterpret_cast<const float4*>(g_T + n * 256 + lane * 4);
        float4 b = *reinterpret_cast<const float4*>(bias + lane * 4);
        float4 r;
        r.x = fmaxf(p.x + acc.x * inv + b.x, 0.f);
        r.y = fmaxf(p.y + acc.y * inv + b.y, 0.f);
        r.z = fmaxf(p.z + acc.z * inv + b.z, 0.f);
        r.w = fmaxf(p.w + acc.w * inv + b.w, 0.f);
        *reinterpret_cast<float4*>(dsta + n * 128 + lane * 4) = r;
    } else {
        float2 acc = make_float2(0.f, 0.f);
        for (int i = s0; i < s1; ++i) {
            int s = g_csr[i];
            float2 v = *reinterpret_cast<const float2*>(g_T + s * 128 + 64 + lane * 2);
            acc.x += v.x; acc.y += v.y;
        }
        float2 p = *reinterpret_cast<const float2*>(g_T + n * 128 + lane * 2);
        float2 b = *reinterpret_cast<const float2*>(bias + lane * 2);
        float2 r;
        r.x = p.x + acc.x * inv + b.x;   // no relu on last layer
        r.y = p.y + acc.y * inv + b.y;
        *reinterpret_cast<float2*>(outext + n * 64 + lane * 2) = r;
    }
}

// ---------------- launch ----------------
extern "C" void kernel_launch(void* const* d_in, const int* in_sizes, int n_in,
                              void* d_out, int out_size) {
    const float* x   = (const float*)d_in[0];
    const int*   src = (const int*)d_in[1];
    const int*   dst = (const int*)d_in[2];
    const float* Ws0 = (const float*)d_in[3];
    const float* Wn0 = (const float*)d_in[4];
    const float* b0  = (const float*)d_in[5];
    const float* Ws1 = (const float*)d_in[6];
    const float* Wn1 = (const float*)d_in[7];
    const float* b1  = (const float*)d_in[8];
    const float* Ws2 = (const float*)d_in[9];
    const float* Wn2 = (const float*)d_in[10];
    const float* b2  = (const float*)d_in[11];
    float* out = (float*)d_out;

    k_zero<<<(NN + 255) / 256, 256>>>();
    k_hist<<<(EE + 255) / 256, 256>>>(dst);
    k_scan<<<1, 1024>>>();
    k_scatter<<<(EE + 255) / 256, 256>>>(src, dst);
    k_concatW<<<(128 * 128 + 255) / 256, 256>>>(Ws0, Wn0, Ws1, Wn1, Ws2, Wn2);

    const int MB = (NN + 127) / 128;        // 391
    const int FB = (NN + 3) / 4;            // 12500

    // Layer 0
    k_gemm<<<dim3(MB, 4), 256>>>(x, -1, 0, 256);
    k_finish<<<FB, 128>>>(b0, nullptr, 0);
    // Layer 1
    k_gemm<<<dim3(MB, 4), 256>>>(nullptr, 0, 1, 256);
    k_finish<<<FB, 128>>>(b1, nullptr, 1);
    // Layer 2
    k_gemm<<<dim3(MB, 2), 256>>>(nullptr, 1, 2, 128);
    k_finish<<<FB, 128>>>(b2, out, 2);
}

// round 3
// speedup vs baseline: 1.6760x; 1.2277x over previous
#include <cuda_runtime.h>
#include <cstdint>

#define NN   50000
#define EE   800000

// ---------------- scratch (no allocations allowed) ----------------
__device__ int   g_cnt[NN];
__device__ int   g_off[NN + 1];
__device__ int   g_cur[NN];
__device__ int   g_csr[EE];
__device__ float g_T[NN * 256];       // per-layer GEMM output [self | neigh]
__device__ float g_h0[NN * 128];
__device__ float g_h1[NN * 128];
__device__ float g_W0[128 * 256];     // [Ws0 | Wn0] column-concat
__device__ float g_W1[128 * 256];
__device__ float g_W2[128 * 128];     // [Ws2 | Wn2]

// ---------------- CSR build ----------------
__global__ void k_zero() {
    int i = blockIdx.x * blockDim.x + threadIdx.x;
    if (i < NN) g_cnt[i] = 0;
}

__global__ void k_hist(const int* __restrict__ dst) {
    int e = blockIdx.x * blockDim.x + threadIdx.x;
    if (e < EE) atomicAdd(&g_cnt[dst[e]], 1);
}

__global__ void k_scan() {
    __shared__ int ss[1024];
    int t = threadIdx.x;
    const int CH = (NN + 1023) / 1024;
    int s = t * CH;
    int e = min(s + CH, NN);
    int local = 0;
    for (int i = s; i < e; ++i) local += g_cnt[i];
    ss[t] = local;
    __syncthreads();
    for (int d = 1; d < 1024; d <<= 1) {
        int v = (t >= d) ? ss[t - d] : 0;
        __syncthreads();
        ss[t] += v;
        __syncthreads();
    }
    int run = (t > 0) ? ss[t - 1] : 0;
    for (int i = s; i < e; ++i) {
        g_off[i] = run;
        g_cur[i] = run;
        run += g_cnt[i];
    }
    if (t == 0) g_off[NN] = EE;
}

__global__ void k_scatter(const int* __restrict__ src, const int* __restrict__ dst) {
    int e = blockIdx.x * blockDim.x + threadIdx.x;
    if (e < EE) {
        int p = atomicAdd(&g_cur[dst[e]], 1);
        g_csr[p] = src[e];
    }
}

// ---------------- weight concat (columns) ----------------
__global__ void k_concatW(const float* __restrict__ Ws0, const float* __restrict__ Wn0,
                          const float* __restrict__ Ws1, const float* __restrict__ Wn1,
                          const float* __restrict__ Ws2, const float* __restrict__ Wn2) {
    int i = blockIdx.x * blockDim.x + threadIdx.x;
    if (i < 128 * 128) {
        int k = i >> 7, c = i & 127;
        g_W0[k * 256 + c]       = Ws0[i];
        g_W0[k * 256 + 128 + c] = Wn0[i];
        g_W1[k * 256 + c]       = Ws1[i];
        g_W1[k * 256 + 128 + c] = Wn1[i];
    }
    if (i < 128 * 64) {
        int k = i >> 6, c = i & 63;
        g_W2[k * 128 + c]      = Ws2[i];
        g_W2[k * 128 + 64 + c] = Wn2[i];
    }
}

// ---------------- bf16 helpers ----------------
// pack two floats into bf16x2 (low half = first/even-k element)
__device__ __forceinline__ uint32_t pack_bf2(float lo, float hi) {
    uint32_t r;
    asm("cvt.rn.bf16x2.f32 %0, %1, %2;" : "=r"(r) : "f"(hi), "f"(lo));
    return r;
}
// split a float pair into hi(bf16x2) and lo(bf16x2 of residual)
__device__ __forceinline__ void split_pair(float a, float b, uint32_t& h, uint32_t& l) {
    h = pack_bf2(a, b);
    float ha = __uint_as_float(h << 16);
    float hb = __uint_as_float(h & 0xffff0000u);
    l = pack_bf2(a - ha, b - hb);
}

__device__ __forceinline__ void mma16(float* c, const uint32_t* a, const uint32_t* b) {
    asm volatile(
        "mma.sync.aligned.m16n8k16.row.col.f32.bf16.bf16.f32 "
        "{%0,%1,%2,%3}, {%4,%5,%6,%7}, {%8,%9}, {%0,%1,%2,%3};\n"
        : "+f"(c[0]), "+f"(c[1]), "+f"(c[2]), "+f"(c[3])
        : "r"(a[0]), "r"(a[1]), "r"(a[2]), "r"(a[3]), "r"(b[0]), "r"(b[1]));
}

// ---------------- GEMM: T[M,nout] = A[M,128] @ W[128,nout] ----------------
// 128x64 block tile, 256 thr = 8 warps (4x2), warp tile 32x32 = 2x4 mma tiles.
// bf16 hi/lo 3-term split (~2^-16 residual); pre-converted packed smem;
// register-prefetch double buffering of k-chunks.
__global__ __launch_bounds__(256) void k_gemm(const float* __restrict__ Aext,
                                              int asel, int wsel, int nout) {
    const float* __restrict__ A =
        (asel == 0) ? g_h0 : (asel == 1) ? g_h1 : Aext;
    const float* __restrict__ W =
        (wsel == 0) ? g_W0 : (wsel == 1) ? g_W1 : g_W2;

    // packed bf16x2 over k: As[m][k2], Bs[k2][n]; strides chosen conflict-free
    __shared__ uint32_t As_h[128][20], As_l[128][20];
    __shared__ uint32_t Bs_h[16][68],  Bs_l[16][68];

    int tid  = threadIdx.x;
    int bm   = blockIdx.x * 128;
    int bn   = blockIdx.y * 64;
    int warp = tid >> 5, lane = tid & 31;
    int wm = (warp & 3) * 32;
    int wn = (warp >> 2) * 32;
    int gi = lane >> 2;
    int ti = lane & 3;

    // A staging coords: 4 float4 per thread (128x32 chunk)
    int a_row = tid >> 3;            // +32 per r
    int a_f4  = (tid & 7) << 2;      // k offset 0..28
    // B staging coords: thread owns one k2 (two k rows) x 4 n
    int b_k2  = tid >> 4;            // 0..15
    int b_f4  = (tid & 15) << 2;     // n offset 0..60

    float c[2][4][4];
#pragma unroll
    for (int mt = 0; mt < 2; ++mt)
#pragma unroll
        for (int nt = 0; nt < 4; ++nt)
#pragma unroll
            for (int i = 0; i < 4; ++i) c[mt][nt][i] = 0.f;

    float4 pa[4];
    float4 pb0, pb1;

    // prefetch chunk 0
#pragma unroll
    for (int r = 0; r < 4; ++r) {
        int gr = bm + a_row + r * 32;
        pa[r] = (gr < NN) ? *reinterpret_cast<const float4*>(A + gr * 128 + a_f4)
                          : make_float4(0.f, 0.f, 0.f, 0.f);
    }
    pb0 = *reinterpret_cast<const float4*>(W + (2 * b_k2) * nout + bn + b_f4);
    pb1 = *reinterpret_cast<const float4*>(W + (2 * b_k2 + 1) * nout + bn + b_f4);

    for (int kc = 0; kc < 4; ++kc) {
        // convert + store staged chunk
#pragma unroll
        for (int r = 0; r < 4; ++r) {
            int row = a_row + r * 32;
            int k2  = a_f4 >> 1;
            uint32_t h0, l0, h1, l1;
            split_pair(pa[r].x, pa[r].y, h0, l0);
            split_pair(pa[r].z, pa[r].w, h1, l1);
            As_h[row][k2] = h0; As_h[row][k2 + 1] = h1;
            As_l[row][k2] = l0; As_l[row][k2 + 1] = l1;
        }
        {
            uint32_t h[4], l[4];
            split_pair(pb0.x, pb1.x, h[0], l[0]);
            split_pair(pb0.y, pb1.y, h[1], l[1]);
            split_pair(pb0.z, pb1.z, h[2], l[2]);
            split_pair(pb0.w, pb1.w, h[3], l[3]);
#pragma unroll
            for (int j = 0; j < 4; ++j) {
                Bs_h[b_k2][b_f4 + j] = h[j];
                Bs_l[b_k2][b_f4 + j] = l[j];
            }
        }
        __syncthreads();

        // prefetch next chunk while computing
        if (kc < 3) {
            int kn = (kc + 1) * 32;
#pragma unroll
            for (int r = 0; r < 4; ++r) {
                int gr = bm + a_row + r * 32;
                pa[r] = (gr < NN)
                    ? *reinterpret_cast<const float4*>(A + gr * 128 + kn + a_f4)
                    : make_float4(0.f, 0.f, 0.f, 0.f);
            }
            pb0 = *reinterpret_cast<const float4*>(W + (kn + 2 * b_k2) * nout + bn + b_f4);
            pb1 = *reinterpret_cast<const float4*>(W + (kn + 2 * b_k2 + 1) * nout + bn + b_f4);
        }

        // compute: 2 k16-steps per 32-k chunk
#pragma unroll
        for (int st = 0; st < 2; ++st) {
            int kb2 = st * 8;
            uint32_t ah[2][4], al[2][4];
#pragma unroll
            for (int mt = 0; mt < 2; ++mt) {
                int rb = wm + mt * 16 + gi;
                ah[mt][0] = As_h[rb][kb2 + ti];
                ah[mt][1] = As_h[rb + 8][kb2 + ti];
                ah[mt][2] = As_h[rb][kb2 + ti + 4];
                ah[mt][3] = As_h[rb + 8][kb2 + ti + 4];
                al[mt][0] = As_l[rb][kb2 + ti];
                al[mt][1] = As_l[rb + 8][kb2 + ti];
                al[mt][2] = As_l[rb][kb2 + ti + 4];
                al[mt][3] = As_l[rb + 8][kb2 + ti + 4];
            }
            uint32_t bh[4][2], bl[4][2];
#pragma unroll
            for (int nt = 0; nt < 4; ++nt) {
                int cb = wn + nt * 8 + gi;
                bh[nt][0] = Bs_h[kb2 + ti][cb];
                bh[nt][1] = Bs_h[kb2 + ti + 4][cb];
                bl[nt][0] = Bs_l[kb2 + ti][cb];
                bl[nt][1] = Bs_l[kb2 + ti + 4][cb];
            }
#pragma unroll
            for (int mt = 0; mt < 2; ++mt)
#pragma unroll
                for (int nt = 0; nt < 4; ++nt) {
                    mma16(c[mt][nt], ah[mt], bh[nt]);
                    mma16(c[mt][nt], al[mt], bh[nt]);
                    mma16(c[mt][nt], ah[mt], bl[nt]);
                }
        }
        __syncthreads();
    }

    // epilogue: raw store (bias/relu fused into k_finish)
#pragma unroll
    for (int mt = 0; mt < 2; ++mt) {
#pragma unroll
        for (int nt = 0; nt < 4; ++nt) {
            int row = bm + wm + mt * 16 + gi;
            int col = bn + wn + nt * 8 + ti * 2;
            if (row < NN)
                *reinterpret_cast<float2*>(g_T + row * nout + col) =
                    make_float2(c[mt][nt][0], c[mt][nt][1]);
            if (row + 8 < NN)
                *reinterpret_cast<float2*>(g_T + (row + 8) * nout + col) =
                    make_float2(c[mt][nt][2], c[mt][nt][3]);
        }
    }
}

// ---------------- finish: out[n] = relu?(T[n,self] + mean_s T[s,neigh] + b) ----
__global__ __launch_bounds__(256) void k_finish(const float* __restrict__ bias,
                                                float* __restrict__ outext, int mode) {
    int warp = threadIdx.x >> 5, lane = threadIdx.x & 31;
    int n = blockIdx.x * 8 + warp;
    if (n >= NN) return;
    int s0 = g_off[n], s1 = g_off[n + 1];
    float inv = 1.0f / (float)((s1 - s0) > 0 ? (s1 - s0) : 1);

    if (mode < 2) {
        float* __restrict__ dsta = mode ? g_h1 : g_h0;
        float4 acc = make_float4(0.f, 0.f, 0.f, 0.f);
        float4 ac2 = make_float4(0.f, 0.f, 0.f, 0.f);
        int i = s0;
        for (; i + 2 <= s1; i += 2) {
            int sa = g_csr[i], sb = g_csr[i + 1];
            float4 va = *reinterpret_cast<const float4*>(g_T + sa * 256 + 128 + lane * 4);
            float4 vb = *reinterpret_cast<const float4*>(g_T + sb * 256 + 128 + lane * 4);
            acc.x += va.x; acc.y += va.y; acc.z += va.z; acc.w += va.w;
            ac2.x += vb.x; ac2.y += vb.y; ac2.z += vb.z; ac2.w += vb.w;
        }
        if (i < s1) {
            int sa = g_csr[i];
            float4 va = *reinterpret_cast<const float4*>(g_T + sa * 256 + 128 + lane * 4);
            acc.x += va.x; acc.y += va.y; acc.z += va.z; acc.w += va.w;
        }
        acc.x += ac2.x; acc.y += ac2.y; acc.z += ac2.z; acc.w += ac2.w;
        float4 p = *reinterpret_cast<const float4*>(g_T + n * 256 + lane * 4);
        float4 b = *reinterpret_cast<const float4*>(bias + lane * 4);
        float4 r;
        r.x = fmaxf(p.x + acc.x * inv + b.x, 0.f);
        r.y = fmaxf(p.y + acc.y * inv + b.y, 0.f);
        r.z = fmaxf(p.z + acc.z * inv + b.z, 0.f);
        r.w = fmaxf(p.w + acc.w * inv + b.w, 0.f);
        *reinterpret_cast<float4*>(dsta + n * 128 + lane * 4) = r;
    } else {
        float2 acc = make_float2(0.f, 0.f);
        float2 ac2 = make_float2(0.f, 0.f);
        int i = s0;
        for (; i + 2 <= s1; i += 2) {
            int sa = g_csr[i], sb = g_csr[i + 1];
            float2 va = *reinterpret_cast<const float2*>(g_T + sa * 128 + 64 + lane * 2);
            float2 vb = *reinterpret_cast<const float2*>(g_T + sb * 128 + 64 + lane * 2);
            acc.x += va.x; acc.y += va.y;
            ac2.x += vb.x; ac2.y += vb.y;
        }
        if (i < s1) {
            int sa = g_csr[i];
            float2 va = *reinterpret_cast<const float2*>(g_T + sa * 128 + 64 + lane * 2);
            acc.x += va.x; acc.y += va.y;
        }
        acc.x += ac2.x; acc.y += ac2.y;
        float2 p = *reinterpret_cast<const float2*>(g_T + n * 128 + lane * 2);
        float2 b = *reinterpret_cast<const float2*>(bias + lane * 2);
        float2 r;
        r.x = p.x + acc.x * inv + b.x;
        r.y = p.y + acc.y * inv + b.y;
        *reinterpret_cast<float2*>(outext + n * 64 + lane * 2) = r;
    }
}

// ---------------- launch ----------------
extern "C" void kernel_launch(void* const* d_in, const int* in_sizes, int n_in,
                              void* d_out, int out_size) {
    const float* x   = (const float*)d_in[0];
    const int*   src = (const int*)d_in[1];
    const int*   dst = (const int*)d_in[2];
    const float* Ws0 = (const float*)d_in[3];
    const float* Wn0 = (const float*)d_in[4];
    const float* b0  = (const float*)d_in[5];
    const float* Ws1 = (const float*)d_in[6];
    const float* Wn1 = (const float*)d_in[7];
    const float* b1  = (const float*)d_in[8];
    const float* Ws2 = (const float*)d_in[9];
    const float* Wn2 = (const float*)d_in[10];
    const float* b2  = (const float*)d_in[11];
    float* out = (float*)d_out;

    k_zero<<<(NN + 255) / 256, 256>>>();
    k_hist<<<(EE + 255) / 256, 256>>>(dst);
    k_scan<<<1, 1024>>>();
    k_scatter<<<(EE + 255) / 256, 256>>>(src, dst);
    k_concatW<<<(128 * 128 + 255) / 256, 256>>>(Ws0, Wn0, Ws1, Wn1, Ws2, Wn2);

    const int MB = (NN + 127) / 128;        // 391
    const int FB = (NN + 7) / 8;            // 6250

    // Layer 0
    k_gemm<<<dim3(MB, 4), 256>>>(x, -1, 0, 256);
    k_finish<<<FB, 256>>>(b0, nullptr, 0);
    // Layer 1
    k_gemm<<<dim3(MB, 4), 256>>>(nullptr, 0, 1, 256);
    k_finish<<<FB, 256>>>(b1, nullptr, 1);
    // Layer 2
    k_gemm<<<dim3(MB, 2), 256>>>(nullptr, 1, 2, 128);
    k_finish<<<FB, 256>>>(b2, out, 2);
}

// round 5
// speedup vs baseline: 1.7878x; 1.0667x over previous
#include <cuda_runtime.h>
#include <cuda_fp16.h>
#include <cstdint>

#define NN   50000
#define EE   800000
#define MT   391          // ceil(NN/128)

// ---------------- scratch (no allocations allowed) ----------------
__device__ int      g_cnt[NN];
__device__ int      g_off[NN + 1];
__device__ int      g_cur[NN];
__device__ int      g_csr[EE];
__device__ float    g_T[NN * 128];            // fp32 self half
__device__ uint32_t g_Tn[NN * 64];            // half2 neighbor payload
__device__ uint32_t g_Ah[MT * 128 * 64];      // activations bf16x2-hi  [row][k2]
__device__ uint32_t g_Al[MT * 128 * 64];      // activations bf16x2-lo
__device__ uint32_t g_Wh[2 * 16384 + 8192];   // weights bf16x2-hi [k2][n]: L0@0 L1@16384 L2@32768
__device__ uint32_t g_Wl[2 * 16384 + 8192];

// ---------------- bf16 helpers (identical to R3, proven) ----------------
__device__ __forceinline__ uint32_t pack_bf2(float lo, float hi) {
    uint32_t r;
    asm("cvt.rn.bf16x2.f32 %0, %1, %2;" : "=r"(r) : "f"(hi), "f"(lo));
    return r;
}
__device__ __forceinline__ void split_pair(float a, float b, uint32_t& h, uint32_t& l) {
    h = pack_bf2(a, b);
    float ha = __uint_as_float(h << 16);
    float hb = __uint_as_float(h & 0xffff0000u);
    l = pack_bf2(a - ha, b - hb);
}
__device__ __forceinline__ void mma16(float* c, const uint32_t* a, const uint32_t* b) {
    asm volatile(
        "mma.sync.aligned.m16n8k16.row.col.f32.bf16.bf16.f32 "
        "{%0,%1,%2,%3}, {%4,%5,%6,%7}, {%8,%9}, {%0,%1,%2,%3};\n"
        : "+f"(c[0]), "+f"(c[1]), "+f"(c[2]), "+f"(c[3])
        : "r"(a[0]), "r"(a[1]), "r"(a[2]), "r"(a[3]), "r"(b[0]), "r"(b[1]));
}

// ---------------- CSR build ----------------
__global__ void k_zero() {
    int i = blockIdx.x * blockDim.x + threadIdx.x;
    if (i < NN) g_cnt[i] = 0;
}
__global__ void k_hist(const int* __restrict__ dst) {
    int e = blockIdx.x * blockDim.x + threadIdx.x;
    if (e < EE) atomicAdd(&g_cnt[dst[e]], 1);
}
__global__ void k_scan() {
    __shared__ int ss[1024];
    int t = threadIdx.x;
    const int CH = (NN + 1023) / 1024;
    int s = t * CH, e = min(s + CH, NN);
    int local = 0;
    for (int i = s; i < e; ++i) local += g_cnt[i];
    ss[t] = local;
    __syncthreads();
    for (int d = 1; d < 1024; d <<= 1) {
        int v = (t >= d) ? ss[t - d] : 0;
        __syncthreads();
        ss[t] += v;
        __syncthreads();
    }
    int run = (t > 0) ? ss[t - 1] : 0;
    for (int i = s; i < e; ++i) {
        g_off[i] = run; g_cur[i] = run; run += g_cnt[i];
    }
    if (t == 0) g_off[NN] = EE;
}
__global__ void k_scatter(const int* __restrict__ src, const int* __restrict__ dst) {
    int e = blockIdx.x * blockDim.x + threadIdx.x;
    if (e < EE) {
        int p = atomicAdd(&g_cur[dst[e]], 1);
        g_csr[p] = src[e];
    }
}

// ---------------- weight prep: [k2][n] packed hi/lo ----------------
__global__ void k_prepW(const float* __restrict__ Ws0, const float* __restrict__ Wn0,
                        const float* __restrict__ Ws1, const float* __restrict__ Wn1,
                        const float* __restrict__ Ws2, const float* __restrict__ Wn2) {
    int id = blockIdx.x * blockDim.x + threadIdx.x;
    if (id >= 40960) return;
    int l, local, wbase, nw;
    if (id < 16384)      { l = 0; local = id;         wbase = 0;     nw = 256; }
    else if (id < 32768) { l = 1; local = id - 16384; wbase = 16384; nw = 256; }
    else                 { l = 2; local = id - 32768; wbase = 32768; nw = 128; }
    int k2 = local / nw;
    int n  = local % nw;
    int k  = k2 * 2;
    int d  = nw >> 1;
    float v0, v1;
    if (l == 0) {
        v0 = (n < d) ? Ws0[k * d + n] : Wn0[k * d + n - d];
        v1 = (n < d) ? Ws0[(k + 1) * d + n] : Wn0[(k + 1) * d + n - d];
    } else if (l == 1) {
        v0 = (n < d) ? Ws1[k * d + n] : Wn1[k * d + n - d];
        v1 = (n < d) ? Ws1[(k + 1) * d + n] : Wn1[(k + 1) * d + n - d];
    } else {
        v0 = (n < d) ? Ws2[k * d + n] : Wn2[k * d + n - d];
        v1 = (n < d) ? Ws2[(k + 1) * d + n] : Wn2[(k + 1) * d + n - d];
    }
    uint32_t h, lo;
    split_pair(v0, v1, h, lo);
    g_Wh[wbase + k2 * nw + n] = h;
    g_Wl[wbase + k2 * nw + n] = lo;
}

// ---------------- x -> packed hi/lo images ----------------
__global__ void k_convX(const float* __restrict__ x) {
    int id = blockIdx.x * blockDim.x + threadIdx.x;
    if (id >= NN * 64) return;
    int n = id >> 6, k2 = id & 63;
    float2 v = *reinterpret_cast<const float2*>(x + n * 128 + k2 * 2);
    uint32_t h, lo;
    split_pair(v.x, v.y, h, lo);
    g_Ah[n * 64 + k2] = h;
    g_Al[n * 64 + k2] = lo;
}

// ---------------- GEMM: 128x128 tile, mma.sync bf16 3-term ----------------
// 8 warps = 4(M) x 2(N); warp tile 32x64 = 2 mt x 8 nt.
__global__ __launch_bounds__(256) void k_gemm(int wb, int wstride, int dsplit,
                                              int tn_str) {
    __shared__ uint32_t As_h[128][20], As_l[128][20];   // row stride 80B (16B-mult)
    __shared__ uint32_t Bs_h[16][136], Bs_l[16][136];   // ti*8+gi banks: conflict-free

    int tid  = threadIdx.x;
    int bm   = blockIdx.x * 128;
    int bn   = blockIdx.y * 128;
    int warp = tid >> 5, lane = tid & 31;
    int wm = (warp & 3) * 32;
    int wn = (warp >> 2) * 64;
    int gi = lane >> 2;
    int ti = lane & 3;

    const uint4* GA_h = reinterpret_cast<const uint4*>(g_Ah);
    const uint4* GA_l = reinterpret_cast<const uint4*>(g_Al);
    const uint4* GW_h = reinterpret_cast<const uint4*>(g_Wh);
    const uint4* GW_l = reinterpret_cast<const uint4*>(g_Wl);
    int wb4 = wb >> 2, bn4 = bn >> 2, ws4 = wstride >> 2;

    // staging coords (2 uint4 per array per thread per chunk)
    int a_row0 = tid >> 2,          a_q0 = tid & 3;          // idx = tid
    int a_row1 = (tid + 256) >> 2,  a_q1 = tid & 3;          // idx = tid+256
    int b_k20 = tid >> 5,           b_n40 = tid & 31;
    int b_k21 = (tid + 256) >> 5,   b_n41 = tid & 31;

    float c[2][8][4];
#pragma unroll
    for (int mt = 0; mt < 2; ++mt)
#pragma unroll
        for (int nt = 0; nt < 8; ++nt)
#pragma unroll
            for (int i = 0; i < 4; ++i) c[mt][nt][i] = 0.f;

    uint4 pAh[2], pAl[2], pBh[2], pBl[2];

#define PREF(kc)                                                                 \
    do {                                                                         \
        pAh[0] = GA_h[(bm + a_row0) * 16 + (kc) * 4 + a_q0];                     \
        pAh[1] = GA_h[(bm + a_row1) * 16 + (kc) * 4 + a_q1];                     \
        pAl[0] = GA_l[(bm + a_row0) * 16 + (kc) * 4 + a_q0];                     \
        pAl[1] = GA_l[(bm + a_row1) * 16 + (kc) * 4 + a_q1];                     \
        pBh[0] = GW_h[wb4 + ((kc) * 16 + b_k20) * ws4 + bn4 + b_n40];            \
        pBh[1] = GW_h[wb4 + ((kc) * 16 + b_k21) * ws4 + bn4 + b_n41];            \
        pBl[0] = GW_l[wb4 + ((kc) * 16 + b_k20) * ws4 + bn4 + b_n40];            \
        pBl[1] = GW_l[wb4 + ((kc) * 16 + b_k21) * ws4 + bn4 + b_n41];            \
    } while (0)

    PREF(0);

    for (int kc = 0; kc < 4; ++kc) {
        *reinterpret_cast<uint4*>(&As_h[a_row0][a_q0 * 4]) = pAh[0];
        *reinterpret_cast<uint4*>(&As_h[a_row1][a_q1 * 4]) = pAh[1];
        *reinterpret_cast<uint4*>(&As_l[a_row0][a_q0 * 4]) = pAl[0];
        *reinterpret_cast<uint4*>(&As_l[a_row1][a_q1 * 4]) = pAl[1];
        *reinterpret_cast<uint4*>(&Bs_h[b_k20][b_n40 * 4]) = pBh[0];
        *reinterpret_cast<uint4*>(&Bs_h[b_k21][b_n41 * 4]) = pBh[1];
        *reinterpret_cast<uint4*>(&Bs_l[b_k20][b_n40 * 4]) = pBl[0];
        *reinterpret_cast<uint4*>(&Bs_l[b_k21][b_n41 * 4]) = pBl[1];
        __syncthreads();

        if (kc < 3) PREF(kc + 1);

#pragma unroll
        for (int st = 0; st < 2; ++st) {
            int kb2 = st * 8;
            uint32_t ah[2][4], al[2][4];
#pragma unroll
            for (int mt = 0; mt < 2; ++mt) {
                int rb = wm + mt * 16 + gi;
                ah[mt][0] = As_h[rb][kb2 + ti];
                ah[mt][1] = As_h[rb + 8][kb2 + ti];
                ah[mt][2] = As_h[rb][kb2 + ti + 4];
                ah[mt][3] = As_h[rb + 8][kb2 + ti + 4];
                al[mt][0] = As_l[rb][kb2 + ti];
                al[mt][1] = As_l[rb + 8][kb2 + ti];
                al[mt][2] = As_l[rb][kb2 + ti + 4];
                al[mt][3] = As_l[rb + 8][kb2 + ti + 4];
            }
#pragma unroll
            for (int nt = 0; nt < 8; ++nt) {
                int cb = wn + nt * 8 + gi;
                uint32_t bh[2], bl[2];
                bh[0] = Bs_h[kb2 + ti][cb];
                bh[1] = Bs_h[kb2 + ti + 4][cb];
                bl[0] = Bs_l[kb2 + ti][cb];
                bl[1] = Bs_l[kb2 + ti + 4][cb];
#pragma unroll
                for (int mt = 0; mt < 2; ++mt) {
                    mma16(c[mt][nt], ah[mt], bh);
                    mma16(c[mt][nt], al[mt], bh);
                    mma16(c[mt][nt], ah[mt], bl);
                }
            }
        }
        __syncthreads();
    }
#undef PREF

    // epilogue: self cols -> fp32 g_T; neighbor cols -> half2 g_Tn
#pragma unroll
    for (int mt = 0; mt < 2; ++mt) {
        int r0 = bm + wm + mt * 16 + gi;
        int r1 = r0 + 8;
#pragma unroll
        for (int nt = 0; nt < 8; ++nt) {
            int colg = bn + wn + nt * 8 + ti * 2;   // global column
            if (colg < dsplit) {
                if (r0 < NN)
                    *reinterpret_cast<float2*>(g_T + r0 * dsplit + colg) =
                        make_float2(c[mt][nt][0], c[mt][nt][1]);
                if (r1 < NN)
                    *reinterpret_cast<float2*>(g_T + r1 * dsplit + colg) =
                        make_float2(c[mt][nt][2], c[mt][nt][3]);
            } else {
                int pc = (colg - dsplit) >> 1;
                if (r0 < NN) {
                    __half2 h2 = __floats2half2_rn(c[mt][nt][0], c[mt][nt][1]);
                    g_Tn[r0 * tn_str + pc] = *reinterpret_cast<uint32_t*>(&h2);
                }
                if (r1 < NN) {
                    __half2 h2 = __floats2half2_rn(c[mt][nt][2], c[mt][nt][3]);
                    g_Tn[r1 * tn_str + pc] = *reinterpret_cast<uint32_t*>(&h2);
                }
            }
        }
    }
}

// ---------------- finish ----------------
// mode 0: h = relu(T_self + mean*inv + b) -> write bf16 hi/lo images (next layer)
// mode 2: out = T_self + mean*inv + b (d=64)
__global__ __launch_bounds__(256) void k_finish(const float* __restrict__ bias,
                                                float* __restrict__ outext, int mode) {
    int warp = threadIdx.x >> 5, lane = threadIdx.x & 31;
    int n = blockIdx.x * 8 + warp;
    if (n >= NN) return;
    int s0 = g_off[n], s1 = g_off[n + 1];
    float inv = 1.0f / (float)((s1 - s0) > 0 ? (s1 - s0) : 1);

    if (mode == 0) {
        float4 acc = make_float4(0.f, 0.f, 0.f, 0.f);
        float4 ac2 = make_float4(0.f, 0.f, 0.f, 0.f);
        int i = s0;
        for (; i + 2 <= s1; i += 2) {
            int sa = g_csr[i], sb = g_csr[i + 1];
            uint2 va = *reinterpret_cast<const uint2*>(g_Tn + sa * 64 + lane * 2);
            uint2 vb = *reinterpret_cast<const uint2*>(g_Tn + sb * 64 + lane * 2);
            float2 a0 = __half22float2(*reinterpret_cast<__half2*>(&va.x));
            float2 a1 = __half22float2(*reinterpret_cast<__half2*>(&va.y));
            float2 b0 = __half22float2(*reinterpret_cast<__half2*>(&vb.x));
            float2 b1 = __half22float2(*reinterpret_cast<__half2*>(&vb.y));
            acc.x += a0.x; acc.y += a0.y; acc.z += a1.x; acc.w += a1.y;
            ac2.x += b0.x; ac2.y += b0.y; ac2.z += b1.x; ac2.w += b1.y;
        }
        if (i < s1) {
            int sa = g_csr[i];
            uint2 va = *reinterpret_cast<const uint2*>(g_Tn + sa * 64 + lane * 2);
            float2 a0 = __half22float2(*reinterpret_cast<__half2*>(&va.x));
            float2 a1 = __half22float2(*reinterpret_cast<__half2*>(&va.y));
            acc.x += a0.x; acc.y += a0.y; acc.z += a1.x; acc.w += a1.y;
        }
        acc.x += ac2.x; acc.y += ac2.y; acc.z += ac2.z; acc.w += ac2.w;
        float4 p = *reinterpret_cast<const float4*>(g_T + n * 128 + lane * 4);
        float4 b = *reinterpret_cast<const float4*>(bias + lane * 4);
        float4 r;
        r.x = fmaxf(p.x + acc.x * inv + b.x, 0.f);
        r.y = fmaxf(p.y + acc.y * inv + b.y, 0.f);
        r.z = fmaxf(p.z + acc.z * inv + b.z, 0.f);
        r.w = fmaxf(p.w + acc.w * inv + b.w, 0.f);
        uint32_t h0, l0, h1, l1;
        split_pair(r.x, r.y, h0, l0);
        split_pair(r.z, r.w, h1, l1);
        int i0 = n * 64 + lane * 2;
        g_Ah[i0] = h0;     g_Al[i0] = l0;
        g_Ah[i0 + 1] = h1; g_Al[i0 + 1] = l1;
    } else {
        float2 acc = make_float2(0.f, 0.f);
        float2 ac2 = make_float2(0.f, 0.f);
        int i = s0;
        for (; i + 2 <= s1; i += 2) {
            int sa = g_csr[i], sb = g_csr[i + 1];
            uint32_t va = g_Tn[sa * 32 + lane];
            uint32_t vb = g_Tn[sb * 32 + lane];
            float2 a = __half22float2(*reinterpret_cast<__half2*>(&va));
            float2 b = __half22float2(*reinterpret_cast<__half2*>(&vb));
            acc.x += a.x; acc.y += a.y;
            ac2.x += b.x; ac2.y += b.y;
        }
        if (i < s1) {
            uint32_t va = g_Tn[g_csr[i] * 32 + lane];
            float2 a = __half22float2(*reinterpret_cast<__half2*>(&va));
            acc.x += a.x; acc.y += a.y;
        }
        acc.x += ac2.x; acc.y += ac2.y;
        float2 p = *reinterpret_cast<const float2*>(g_T + n * 64 + lane * 2);
        float2 b = *reinterpret_cast<const float2*>(bias + lane * 2);
        float2 r;
        r.x = p.x + acc.x * inv + b.x;
        r.y = p.y + acc.y * inv + b.y;
        *reinterpret_cast<float2*>(outext + n * 64 + lane * 2) = r;
    }
}

// ---------------- launch ----------------
extern "C" void kernel_launch(void* const* d_in, const int* in_sizes, int n_in,
                              void* d_out, int out_size) {
    const float* x   = (const float*)d_in[0];
    const int*   src = (const int*)d_in[1];
    const int*   dst = (const int*)d_in[2];
    const float* Ws0 = (const float*)d_in[3];
    const float* Wn0 = (const float*)d_in[4];
    const float* b0  = (const float*)d_in[5];
    const float* Ws1 = (const float*)d_in[6];
    const float* Wn1 = (const float*)d_in[7];
    const float* b1  = (const float*)d_in[8];
    const float* Ws2 = (const float*)d_in[9];
    const float* Wn2 = (const float*)d_in[10];
    const float* b2  = (const float*)d_in[11];
    float* out = (float*)d_out;

    k_zero<<<(NN + 255) / 256, 256>>>();
    k_hist<<<(EE + 255) / 256, 256>>>(dst);
    k_scan<<<1, 1024>>>();
    k_scatter<<<(EE + 255) / 256, 256>>>(src, dst);
    k_prepW<<<160, 256>>>(Ws0, Wn0, Ws1, Wn1, Ws2, Wn2);
    k_convX<<<(NN * 64 + 255) / 256, 256>>>(x);

    const int FB = (NN + 7) / 8;

    // Layer 0: [self | neigh] over 256 cols, dsplit 128
    k_gemm<<<dim3(MT, 2), 256>>>(0, 256, 128, 64);
    k_finish<<<FB, 256>>>(b0, nullptr, 0);
    // Layer 1
    k_gemm<<<dim3(MT, 2), 256>>>(16384, 256, 128, 64);
    k_finish<<<FB, 256>>>(b1, nullptr, 0);
    // Layer 2: 128 cols, dsplit 64
    k_gemm<<<dim3(MT, 1), 256>>>(32768, 128, 64, 32);
    k_finish<<<FB, 256>>>(b2, out, 2);
}

// round 7
// speedup vs baseline: 2.5147x; 1.4066x over previous
#include <cuda_runtime.h>
#include <cuda_fp16.h>
#include <cstdint>

#define NN   50000
#define EE   800000
#define MT   391          // ceil(NN/128)
#define SB   98           // scan blocks (512 each)

// ---------------- scratch (no allocations allowed) ----------------
__device__ int      g_cnt[NN];
__device__ int      g_off[NN + 1];
__device__ int      g_cur[NN];
__device__ int      g_csr[EE];
__device__ int      g_bsum[SB];
__device__ int      g_boff[SB];
__device__ float    g_T[NN * 128];            // fp32 self half
__device__ uint32_t g_Tn[NN * 64];            // half2 neighbor payload
__device__ uint32_t g_Ah[MT * 128 * 64];      // activations bf16x2-hi [row][k2]
__device__ uint32_t g_Al[MT * 128 * 64];      // activations bf16x2-lo
__device__ uint32_t g_Wh[2 * 16384 + 8192];   // weights bf16x2-hi [k2][n]
__device__ uint32_t g_Wl[2 * 16384 + 8192];

// ---------------- bf16 helpers ----------------
__device__ __forceinline__ uint32_t pack_bf2(float lo, float hi) {
    uint32_t r;
    asm("cvt.rn.bf16x2.f32 %0, %1, %2;" : "=r"(r) : "f"(hi), "f"(lo));
    return r;
}
__device__ __forceinline__ void split_pair(float a, float b, uint32_t& h, uint32_t& l) {
    h = pack_bf2(a, b);
    float ha = __uint_as_float(h << 16);
    float hb = __uint_as_float(h & 0xffff0000u);
    l = pack_bf2(a - ha, b - hb);
}
__device__ __forceinline__ void mma16(float* c, const uint32_t* a, const uint32_t* b) {
    asm volatile(
        "mma.sync.aligned.m16n8k16.row.col.f32.bf16.bf16.f32 "
        "{%0,%1,%2,%3}, {%4,%5,%6,%7}, {%8,%9}, {%0,%1,%2,%3};\n"
        : "+f"(c[0]), "+f"(c[1]), "+f"(c[2]), "+f"(c[3])
        : "r"(a[0]), "r"(a[1]), "r"(a[2]), "r"(a[3]), "r"(b[0]), "r"(b[1]));
}

// ---------------- fused prep: zero counts + weight/x conversion ----------------
__global__ void k_prep(const float* __restrict__ x,
                       const float* __restrict__ Ws0, const float* __restrict__ Wn0,
                       const float* __restrict__ Ws1, const float* __restrict__ Wn1,
                       const float* __restrict__ Ws2, const float* __restrict__ Wn2) {
    int id = blockIdx.x * blockDim.x + threadIdx.x;
    if (id < NN) g_cnt[id] = 0;
    if (id < 40960) {
        int l, local, wbase, nw;
        if (id < 16384)      { l = 0; local = id;         wbase = 0;     nw = 256; }
        else if (id < 32768) { l = 1; local = id - 16384; wbase = 16384; nw = 256; }
        else                 { l = 2; local = id - 32768; wbase = 32768; nw = 128; }
        int k2 = local / nw, n = local % nw, k = k2 * 2, d = nw >> 1;
        float v0, v1;
        if (l == 0) {
            v0 = (n < d) ? Ws0[k * d + n] : Wn0[k * d + n - d];
            v1 = (n < d) ? Ws0[(k + 1) * d + n] : Wn0[(k + 1) * d + n - d];
        } else if (l == 1) {
            v0 = (n < d) ? Ws1[k * d + n] : Wn1[k * d + n - d];
            v1 = (n < d) ? Ws1[(k + 1) * d + n] : Wn1[(k + 1) * d + n - d];
        } else {
            v0 = (n < d) ? Ws2[k * d + n] : Wn2[k * d + n - d];
            v1 = (n < d) ? Ws2[(k + 1) * d + n] : Wn2[(k + 1) * d + n - d];
        }
        uint32_t h, lo;
        split_pair(v0, v1, h, lo);
        g_Wh[wbase + k2 * nw + n] = h;
        g_Wl[wbase + k2 * nw + n] = lo;
    }
    if (id < NN * 64) {
        int n = id >> 6, k2 = id & 63;
        float2 v = *reinterpret_cast<const float2*>(x + n * 128 + k2 * 2);
        uint32_t h, lo;
        split_pair(v.x, v.y, h, lo);
        g_Ah[n * 64 + k2] = h;
        g_Al[n * 64 + k2] = lo;
    }
}

// ---------------- CSR build ----------------
__global__ void k_hist(const int* __restrict__ dst) {
    int e = blockIdx.x * blockDim.x + threadIdx.x;
    if (e < EE) atomicAdd(&g_cnt[dst[e]], 1);
}

__global__ __launch_bounds__(512) void k_scanA() {
    __shared__ int ss[512];
    int t = threadIdx.x, i = blockIdx.x * 512 + t;
    ss[t] = (i < NN) ? g_cnt[i] : 0;
    __syncthreads();
    for (int d = 256; d > 0; d >>= 1) {
        if (t < d) ss[t] += ss[t + d];
        __syncthreads();
    }
    if (t == 0) g_bsum[blockIdx.x] = ss[0];
}
__global__ void k_scanB() {
    __shared__ int ss[128];
    int t = threadIdx.x;
    ss[t] = (t < SB) ? g_bsum[t] : 0;
    __syncthreads();
    for (int d = 1; d < 128; d <<= 1) {
        int v = (t >= d) ? ss[t - d] : 0;
        __syncthreads();
        ss[t] += v;
        __syncthreads();
    }
    if (t < SB) g_boff[t] = (t > 0) ? ss[t - 1] : 0;
}
__global__ __launch_bounds__(512) void k_scanC() {
    __shared__ int ss[512];
    int t = threadIdx.x, i = blockIdx.x * 512 + t;
    int v0 = (i < NN) ? g_cnt[i] : 0;
    ss[t] = v0;
    __syncthreads();
    for (int d = 1; d < 512; d <<= 1) {
        int v = (t >= d) ? ss[t - d] : 0;
        __syncthreads();
        ss[t] += v;
        __syncthreads();
    }
    if (i < NN) {
        int off = g_boff[blockIdx.x] + ss[t] - v0;
        g_off[i] = off;
        g_cur[i] = off;
    }
    if (i == NN - 1) g_off[NN] = EE;
}
__global__ void k_scatter(const int* __restrict__ src, const int* __restrict__ dst) {
    int e = blockIdx.x * blockDim.x + threadIdx.x;
    if (e < EE) {
        int p = atomicAdd(&g_cur[dst[e]], 1);
        g_csr[p] = src[e];
    }
}

// ---------------- GEMM: 128 x NC tile, 512 threads, dynamic smem ----------------
// 16 warps = 4(M) x 4(N); warp tile 32 x NC/4 = 2 mt x (NC/32) nt.
template <int NC>
__global__ __launch_bounds__(512) void k_gemm(int wb, int dsplit, int tn_str) {
    constexpr int NT = NC / 32;           // nt per warp
    constexpr int BP = NC + 8;            // Bs row stride (u32)
    constexpr int NB = NC / 128;          // B uint4 per thread per buf

    extern __shared__ uint32_t sm[];
    uint32_t (*As_h)[20] = reinterpret_cast<uint32_t(*)[20]>(sm);
    uint32_t (*As_l)[20] = reinterpret_cast<uint32_t(*)[20]>(sm + 2560);
    uint32_t (*Bs_h)[BP] = reinterpret_cast<uint32_t(*)[BP]>(sm + 5120);
    uint32_t (*Bs_l)[BP] = reinterpret_cast<uint32_t(*)[BP]>(sm + 5120 + 16 * BP);

    int tid  = threadIdx.x;
    int bm   = blockIdx.x * 128;
    int warp = tid >> 5, lane = tid & 31;
    int wm = (warp & 3) * 32;
    int wn = (warp >> 2) * (NC / 4);
    int gi = lane >> 2;
    int ti = lane & 3;

    const uint4* GA_h = reinterpret_cast<const uint4*>(g_Ah);
    const uint4* GA_l = reinterpret_cast<const uint4*>(g_Al);
    const uint4* GW_h = reinterpret_cast<const uint4*>(g_Wh);
    const uint4* GW_l = reinterpret_cast<const uint4*>(g_Wl);
    int wb4 = wb >> 2;

    int a_row = tid >> 2, a_q = tid & 3;

    float c[2][NT][4];
#pragma unroll
    for (int mt = 0; mt < 2; ++mt)
#pragma unroll
        for (int nt = 0; nt < NT; ++nt)
#pragma unroll
            for (int i = 0; i < 4; ++i) c[mt][nt][i] = 0.f;

    uint4 pAh, pAl, pBh[NB], pBl[NB];

#define PREF(kc)                                                                  \
    do {                                                                          \
        pAh = GA_h[(bm + a_row) * 16 + (kc) * 4 + a_q];                           \
        pAl = GA_l[(bm + a_row) * 16 + (kc) * 4 + a_q];                           \
        _Pragma("unroll")                                                         \
        for (int j = 0; j < NB; ++j) {                                            \
            int idx = tid + j * 512;                                              \
            int kr = idx / (NC / 4), c4 = idx % (NC / 4);                         \
            pBh[j] = GW_h[wb4 + (((kc) * 16 + kr) * NC >> 2) + c4];               \
            pBl[j] = GW_l[wb4 + (((kc) * 16 + kr) * NC >> 2) + c4];               \
        }                                                                         \
    } while (0)

    PREF(0);

    for (int kc = 0; kc < 4; ++kc) {
        *reinterpret_cast<uint4*>(&As_h[a_row][a_q * 4]) = pAh;
        *reinterpret_cast<uint4*>(&As_l[a_row][a_q * 4]) = pAl;
#pragma unroll
        for (int j = 0; j < NB; ++j) {
            int idx = tid + j * 512;
            int kr = idx / (NC / 4), c4 = idx % (NC / 4);
            *reinterpret_cast<uint4*>(&Bs_h[kr][c4 * 4]) = pBh[j];
            *reinterpret_cast<uint4*>(&Bs_l[kr][c4 * 4]) = pBl[j];
        }
        __syncthreads();

        if (kc < 3) PREF(kc + 1);

#pragma unroll
        for (int st = 0; st < 2; ++st) {
            int kb2 = st * 8;
            uint32_t ah[2][4], al[2][4];
#pragma unroll
            for (int mt = 0; mt < 2; ++mt) {
                int rb = wm + mt * 16 + gi;
                ah[mt][0] = As_h[rb][kb2 + ti];
                ah[mt][1] = As_h[rb + 8][kb2 + ti];
                ah[mt][2] = As_h[rb][kb2 + ti + 4];
                ah[mt][3] = As_h[rb + 8][kb2 + ti + 4];
                al[mt][0] = As_l[rb][kb2 + ti];
                al[mt][1] = As_l[rb + 8][kb2 + ti];
                al[mt][2] = As_l[rb][kb2 + ti + 4];
                al[mt][3] = As_l[rb + 8][kb2 + ti + 4];
            }
#pragma unroll
            for (int nt = 0; nt < NT; ++nt) {
                int cb = wn + nt * 8 + gi;
                uint32_t bh[2], bl[2];
                bh[0] = Bs_h[kb2 + ti][cb];
                bh[1] = Bs_h[kb2 + ti + 4][cb];
                bl[0] = Bs_l[kb2 + ti][cb];
                bl[1] = Bs_l[kb2 + ti + 4][cb];
#pragma unroll
                for (int mt = 0; mt < 2; ++mt) {
                    mma16(c[mt][nt], ah[mt], bh);
                    mma16(c[mt][nt], al[mt], bh);
                    mma16(c[mt][nt], ah[mt], bl);
                }
            }
        }
        __syncthreads();
    }
#undef PREF

    // epilogue: self cols -> fp32 g_T; neighbor cols -> half2 g_Tn
#pragma unroll
    for (int mt = 0; mt < 2; ++mt) {
        int r0 = bm + wm + mt * 16 + gi;
        int r1 = r0 + 8;
#pragma unroll
        for (int nt = 0; nt < NT; ++nt) {
            int colg = wn + nt * 8 + ti * 2;
            if (colg < dsplit) {
                if (r0 < NN)
                    *reinterpret_cast<float2*>(g_T + r0 * dsplit + colg) =
                        make_float2(c[mt][nt][0], c[mt][nt][1]);
                if (r1 < NN)
                    *reinterpret_cast<float2*>(g_T + r1 * dsplit + colg) =
                        make_float2(c[mt][nt][2], c[mt][nt][3]);
            } else {
                int pc = (colg - dsplit) >> 1;
                if (r0 < NN) {
                    __half2 h2 = __floats2half2_rn(c[mt][nt][0], c[mt][nt][1]);
                    g_Tn[r0 * tn_str + pc] = *reinterpret_cast<uint32_t*>(&h2);
                }
                if (r1 < NN) {
                    __half2 h2 = __floats2half2_rn(c[mt][nt][2], c[mt][nt][3]);
                    g_Tn[r1 * tn_str + pc] = *reinterpret_cast<uint32_t*>(&h2);
                }
            }
        }
    }
}

// ---------------- finish ----------------
__global__ __launch_bounds__(256) void k_finish(const float* __restrict__ bias,
                                                float* __restrict__ outext, int mode) {
    int warp = threadIdx.x >> 5, lane = threadIdx.x & 31;
    int n = blockIdx.x * 8 + warp;
    if (n >= NN) return;
    int s0 = g_off[n], s1 = g_off[n + 1];
    float inv = 1.0f / (float)((s1 - s0) > 0 ? (s1 - s0) : 1);

    if (mode == 0) {
        float4 acc = make_float4(0.f, 0.f, 0.f, 0.f);
        float4 ac2 = make_float4(0.f, 0.f, 0.f, 0.f);
        int i = s0;
        for (; i + 2 <= s1; i += 2) {
            int sa = g_csr[i], sb = g_csr[i + 1];
            uint2 va = *reinterpret_cast<const uint2*>(g_Tn + sa * 64 + lane * 2);
            uint2 vb = *reinterpret_cast<const uint2*>(g_Tn + sb * 64 + lane * 2);
            float2 a0 = __half22float2(*reinterpret_cast<__half2*>(&va.x));
            float2 a1 = __half22float2(*reinterpret_cast<__half2*>(&va.y));
            float2 b0 = __half22float2(*reinterpret_cast<__half2*>(&vb.x));
            float2 b1 = __half22float2(*reinterpret_cast<__half2*>(&vb.y));
            acc.x += a0.x; acc.y += a0.y; acc.z += a1.x; acc.w += a1.y;
            ac2.x += b0.x; ac2.y += b0.y; ac2.z += b1.x; ac2.w += b1.y;
        }
        if (i < s1) {
            uint2 va = *reinterpret_cast<const uint2*>(g_Tn + g_csr[i] * 64 + lane * 2);
            float2 a0 = __half22float2(*reinterpret_cast<__half2*>(&va.x));
            float2 a1 = __half22float2(*reinterpret_cast<__half2*>(&va.y));
            acc.x += a0.x; acc.y += a0.y; acc.z += a1.x; acc.w += a1.y;
        }
        acc.x += ac2.x; acc.y += ac2.y; acc.z += ac2.z; acc.w += ac2.w;
        float4 p = *reinterpret_cast<const float4*>(g_T + n * 128 + lane * 4);
        float4 b = *reinterpret_cast<const float4*>(bias + lane * 4);
        float4 r;
        r.x = fmaxf(p.x + acc.x * inv + b.x, 0.f);
        r.y = fmaxf(p.y + acc.y * inv + b.y, 0.f);
        r.z = fmaxf(p.z + acc.z * inv + b.z, 0.f);
        r.w = fmaxf(p.w + acc.w * inv + b.w, 0.f);
        uint32_t h0, l0, h1, l1;
        split_pair(r.x, r.y, h0, l0);
        split_pair(r.z, r.w, h1, l1);
        int i0 = n * 64 + lane * 2;
        g_Ah[i0] = h0;     g_Al[i0] = l0;
        g_Ah[i0 + 1] = h1; g_Al[i0 + 1] = l1;
    } else {
        float2 acc = make_float2(0.f, 0.f);
        float2 ac2 = make_float2(0.f, 0.f);
        int i = s0;
        for (; i + 2 <= s1; i += 2) {
            uint32_t va = g_Tn[g_csr[i] * 32 + lane];
            uint32_t vb = g_Tn[g_csr[i + 1] * 32 + lane];
            float2 a = __half22float2(*reinterpret_cast<__half2*>(&va));
            float2 b = __half22float2(*reinterpret_cast<__half2*>(&vb));
            acc.x += a.x; acc.y += a.y;
            ac2.x += b.x; ac2.y += b.y;
        }
        if (i < s1) {
            uint32_t va = g_Tn[g_csr[i] * 32 + lane];
            float2 a = __half22float2(*reinterpret_cast<__half2*>(&va));
            acc.x += a.x; acc.y += a.y;
        }
        acc.x += ac2.x; acc.y += ac2.y;
        float2 p = *reinterpret_cast<const float2*>(g_T + n * 64 + lane * 2);
        float2 b = *reinterpret_cast<const float2*>(bias + lane * 2);
        float2 r;
        r.x = p.x + acc.x * inv + b.x;
        r.y = p.y + acc.y * inv + b.y;
        *reinterpret_cast<float2*>(outext + n * 64 + lane * 2) = r;
    }
}

// ---------------- launch ----------------
extern "C" void kernel_launch(void* const* d_in, const int* in_sizes, int n_in,
                              void* d_out, int out_size) {
    const float* x   = (const float*)d_in[0];
    const int*   src = (const int*)d_in[1];
    const int*   dst = (const int*)d_in[2];
    const float* Ws0 = (const float*)d_in[3];
    const float* Wn0 = (const float*)d_in[4];
    const float* b0  = (const float*)d_in[5];
    const float* Ws1 = (const float*)d_in[6];
    const float* Wn1 = (const float*)d_in[7];
    const float* b1  = (const float*)d_in[8];
    const float* Ws2 = (const float*)d_in[9];
    const float* Wn2 = (const float*)d_in[10];
    const float* b2  = (const float*)d_in[11];
    float* out = (float*)d_out;

    // dynamic smem sizes: As (20KB) + Bs (2 * 16 * (NC+8) * 4)
    const int SM256 = 20480 + 2 * 16 * 264 * 4;   // 54272
    const int SM128 = 20480 + 2 * 16 * 136 * 4;   // 37888
    cudaFuncSetAttribute(k_gemm<256>, cudaFuncAttributeMaxDynamicSharedMemorySize, SM256);
    cudaFuncSetAttribute(k_gemm<128>, cudaFuncAttributeMaxDynamicSharedMemorySize, SM128);

    k_prep<<<(NN * 64 + 255) / 256, 256>>>(x, Ws0, Wn0, Ws1, Wn1, Ws2, Wn2);
    k_hist<<<(EE + 255) / 256, 256>>>(dst);
    k_scanA<<<SB, 512>>>();
    k_scanB<<<1, 128>>>();
    k_scanC<<<SB, 512>>>();
    k_scatter<<<(EE + 255) / 256, 256>>>(src, dst);

    const int FB = (NN + 7) / 8;

    // Layer 0
    k_gemm<256><<<MT, 512, SM256>>>(0, 128, 64);
    k_finish<<<FB, 256>>>(b0, nullptr, 0);
    // Layer 1
    k_gemm<256><<<MT, 512, SM256>>>(16384, 128, 64);
    k_finish<<<FB, 256>>>(b1, nullptr, 0);
    // Layer 2
    k_gemm<128><<<MT, 512, SM128>>>(32768, 64, 32);
    k_finish<<<FB, 256>>>(b2, out, 2);
}